// round 1
// baseline (speedup 1.0000x reference)
#include <cuda_runtime.h>
#include <math.h>

// Problem constants
#define BATCH 16
#define DIM   384
#define QC    192
#define HW    4096
#define HEADS 8
#define DC    48

// ---------------- scratch (single __device__ global, no allocs) -------------
// layout (floats):
//   g_k    [BATCH*DIM*HW]   = 25165824
//   g_q    [BATCH*DIM*HW]   = 25165824
//   g_rq   [BATCH*DIM]      = 6144
//   g_rk   [BATCH*DIM]      = 6144
//   g_attn [BATCH*HEADS*DC*DC] = 294912
//   g_C    [BATCH*DIM*DIM]  = 2359296
//   g_D    [BATCH*DIM*DIM]  = 2359296
#define OFF_K    0L
#define OFF_Q    25165824L
#define OFF_RQ   50331648L
#define OFF_RK   50337792L
#define OFF_ATTN 50343936L
#define OFF_C    50638848L
#define OFF_D    52998144L
#define SCRATCH_TOTAL 55357440L

__device__ float g_scratch[SCRATCH_TOTAL];

// ---------------- generic batched SGEMM: C = A @ B ---------------------------
// A: [M,K] row-major (lda=K), B: [K,N] row-major (ldb=N), C: [M,N] (ldc=N)
// per-batch strides sA/sB/sC (0 => shared across batch).
// BM=BN=128, BK=16, 256 threads, 8x8 per thread. M%128==0, N%128==0, K%16==0.
__global__ __launch_bounds__(256) void sgemm_kernel(
    const float* __restrict__ A, long sA,
    const float* __restrict__ B, long sB,
    float* __restrict__ C, long sC,
    int M, int N, int K)
{
    const int b = blockIdx.z;
    A += (long)b * sA;
    B += (long)b * sB;
    C += (long)b * sC;
    const int m0 = blockIdx.y * 128;
    const int n0 = blockIdx.x * 128;

    __shared__ float As[16][128];
    __shared__ float Bs[16][128];

    const int tid = threadIdx.x;
    const int tx = tid & 15;      // 0..15 -> 8 cols each
    const int ty = tid >> 4;      // 0..15 -> 8 rows each

    float acc[8][8];
#pragma unroll
    for (int i = 0; i < 8; i++)
#pragma unroll
        for (int j = 0; j < 8; j++) acc[i][j] = 0.0f;

    for (int k0 = 0; k0 < K; k0 += 16) {
        // load A tile 128x16 -> As[k][m]
#pragma unroll
        for (int i = 0; i < 8; i++) {
            int idx = tid + i * 256;          // 0..2047
            int m = idx >> 4, k = idx & 15;
            As[k][m] = A[(long)(m0 + m) * K + (k0 + k)];
        }
        // load B tile 16x128 -> Bs[k][n]
#pragma unroll
        for (int i = 0; i < 8; i++) {
            int idx = tid + i * 256;
            int k = idx >> 7, n = idx & 127;
            Bs[k][n] = B[(long)(k0 + k) * N + (n0 + n)];
        }
        __syncthreads();

#pragma unroll
        for (int kk = 0; kk < 16; kk++) {
            float4 a0 = *(const float4*)&As[kk][ty * 8];
            float4 a1 = *(const float4*)&As[kk][ty * 8 + 4];
            float4 b0 = *(const float4*)&Bs[kk][tx * 8];
            float4 b1 = *(const float4*)&Bs[kk][tx * 8 + 4];
            float a[8] = {a0.x, a0.y, a0.z, a0.w, a1.x, a1.y, a1.z, a1.w};
            float bb[8] = {b0.x, b0.y, b0.z, b0.w, b1.x, b1.y, b1.z, b1.w};
#pragma unroll
            for (int i = 0; i < 8; i++)
#pragma unroll
                for (int j = 0; j < 8; j++)
                    acc[i][j] = fmaf(a[i], bb[j], acc[i][j]);
        }
        __syncthreads();
    }

#pragma unroll
    for (int i = 0; i < 8; i++) {
        float* cp = C + (long)(m0 + ty * 8 + i) * N + n0 + tx * 8;
        float4 v0 = make_float4(acc[i][0], acc[i][1], acc[i][2], acc[i][3]);
        float4 v1 = make_float4(acc[i][4], acc[i][5], acc[i][6], acc[i][7]);
        *(float4*)cp = v0;
        *(float4*)(cp + 4) = v1;
    }
}

// ---------------- row L2 inverse norms (q rows then k rows) ------------------
// grid.x = 2*BATCH*DIM; 256 threads; each block reduces one row of HW floats.
__global__ __launch_bounds__(256) void norm_kernel(float* __restrict__ scratch)
{
    const int row = blockIdx.x;
    const bool is_q = (row < BATCH * DIM);
    const float* p = is_q ? (scratch + OFF_Q + (long)row * HW)
                          : (scratch + OFF_K + (long)(row - BATCH * DIM) * HW);
    const float4* p4 = (const float4*)p;
    float s = 0.0f;
    for (int i = threadIdx.x; i < HW / 4; i += 256) {
        float4 v = p4[i];
        s += v.x * v.x + v.y * v.y + v.z * v.z + v.w * v.w;
    }
#pragma unroll
    for (int o = 16; o; o >>= 1) s += __shfl_xor_sync(0xFFFFFFFFu, s, o);
    __shared__ float ws[8];
    if ((threadIdx.x & 31) == 0) ws[threadIdx.x >> 5] = s;
    __syncthreads();
    if (threadIdx.x == 0) {
        float t = 0.0f;
#pragma unroll
        for (int i = 0; i < 8; i++) t += ws[i];
        float inv = 1.0f / fmaxf(sqrtf(t), 1e-12f);
        if (is_q) scratch[OFF_RQ + row] = inv;
        else      scratch[OFF_RK + (row - BATCH * DIM)] = inv;
    }
}

// ---------------- per-(b,head) attention logits + softmax --------------------
// grid.x = BATCH*HEADS = 128 blocks, 256 threads (16x16 -> 3x3 of 48x48).
__global__ __launch_bounds__(256) void attn_kernel(
    const float* __restrict__ temp, float* __restrict__ scratch)
{
    const int bh = blockIdx.x;
    const int b = bh >> 3, h = bh & 7;
    const float* qp = scratch + OFF_Q + ((long)b * DIM + h * DC) * HW;
    const float* kp = scratch + OFF_K + ((long)b * DIM + h * DC) * HW;
    const float* rq = scratch + OFF_RQ + (long)b * DIM + h * DC;
    const float* rk = scratch + OFF_RK + (long)b * DIM + h * DC;
    float* aout = scratch + OFF_ATTN + (long)bh * DC * DC;

    __shared__ float qs[DC][33];
    __shared__ float ks[DC][33];
    __shared__ float Ss[DC][DC];

    const int tid = threadIdx.x;
    const int tx = tid & 15, ty = tid >> 4;

    float acc[3][3] = {{0, 0, 0}, {0, 0, 0}, {0, 0, 0}};

    for (int s0 = 0; s0 < HW; s0 += 32) {
#pragma unroll
        for (int i = 0; i < 6; i++) {
            int idx = tid + i * 256;          // 0..1535
            int c = idx >> 5, kk = idx & 31;
            qs[c][kk] = qp[(long)c * HW + s0 + kk];
            ks[c][kk] = kp[(long)c * HW + s0 + kk];
        }
        __syncthreads();
#pragma unroll
        for (int kk = 0; kk < 32; kk++) {
            float qa[3], ka[3];
#pragma unroll
            for (int i = 0; i < 3; i++) qa[i] = qs[ty * 3 + i][kk];
#pragma unroll
            for (int j = 0; j < 3; j++) ka[j] = ks[tx * 3 + j][kk];
#pragma unroll
            for (int i = 0; i < 3; i++)
#pragma unroll
                for (int j = 0; j < 3; j++)
                    acc[i][j] = fmaf(qa[i], ka[j], acc[i][j]);
        }
        __syncthreads();
    }

    const float tscale = temp[h];
#pragma unroll
    for (int i = 0; i < 3; i++)
#pragma unroll
        for (int j = 0; j < 3; j++) {
            int c = ty * 3 + i, d = tx * 3 + j;
            Ss[c][d] = acc[i][j] * rq[c] * rk[d] * tscale;
        }
    __syncthreads();

    if (tid < DC) {
        const int c = tid;
        float mx = -1e30f;
#pragma unroll
        for (int d = 0; d < DC; d++) mx = fmaxf(mx, Ss[c][d]);
        float sum = 0.0f;
#pragma unroll
        for (int d = 0; d < DC; d++) {
            float e = expf(Ss[c][d] - mx);
            Ss[c][d] = e;
            sum += e;
        }
        float inv = 1.0f / sum;
#pragma unroll
        for (int d = 0; d < DC; d++) aout[(long)c * DC + d] = Ss[c][d] * inv;
    }
}

// ---------------- fold: C[b] = W_proj @ blockdiag(attn[b]) -------------------
// grid (576, BATCH), 256 threads; one output element per thread.
__global__ __launch_bounds__(256) void fold_kernel(
    const float* __restrict__ wp, float* __restrict__ scratch)
{
    const int b = blockIdx.y;
    const int idx = blockIdx.x * 256 + threadIdx.x;   // 0..147455
    const int o = idx / DIM, m = idx % DIM;
    const int h = m / DC, d = m % DC;
    const float* A = scratch + OFF_ATTN + ((long)b * HEADS + h) * DC * DC;
    const float* w = wp + (long)o * DIM + h * DC;
    float s = 0.0f;
#pragma unroll
    for (int c = 0; c < DC; c++) s = fmaf(w[c], A[c * DC + d], s);
    scratch[OFF_C + ((long)b * DIM + o) * DIM + m] = s;
}

// ---------------- launch ----------------------------------------------------
extern "C" void kernel_launch(void* const* d_in, const int* in_sizes, int n_in,
                              void* d_out, int out_size)
{
    const float* x      = (const float*)d_in[0];  // [16,384,64,64]
    const float* query  = (const float*)d_in[1];  // [16,192,64,64]
    const float* w_kv   = (const float*)d_in[2];  // [768,384]
    const float* w_q    = (const float*)d_in[3];  // [384,192]
    const float* w_proj = (const float*)d_in[4];  // [384,384]
    const float* temp   = (const float*)d_in[5];  // [8,1,1]
    float* out = (float*)d_out;                   // [16,384,64,64]

    float* scratch = nullptr;
    cudaGetSymbolAddress((void**)&scratch, g_scratch);

    const float* w_k = w_kv;                      // rows 0..383
    const float* w_v = w_kv + (long)DIM * DIM;    // rows 384..767

    // 1) k[b] = W_k @ x[b]   : M=384, N=4096, K=384
    sgemm_kernel<<<dim3(HW / 128, DIM / 128, BATCH), 256>>>(
        w_k, 0L, x, (long)DIM * HW, scratch + OFF_K, (long)DIM * HW,
        DIM, HW, DIM);

    // 2) q[b] = W_q @ query[b] : M=384, N=4096, K=192
    sgemm_kernel<<<dim3(HW / 128, DIM / 128, BATCH), 256>>>(
        w_q, 0L, query, (long)QC * HW, scratch + OFF_Q, (long)DIM * HW,
        DIM, HW, QC);

    // 3) inverse L2 norms for all q and k rows
    norm_kernel<<<2 * BATCH * DIM, 256>>>(scratch);

    // 4) attention logits + softmax per (b,head)
    attn_kernel<<<BATCH * HEADS, 256>>>(temp, scratch);

    // 5) C[b] = W_proj @ blockdiag(attn[b])
    fold_kernel<<<dim3((DIM * DIM) / 256, BATCH), 256>>>(w_proj, scratch);

    // 6) D[b] = C[b] @ W_v  : M=384, N=384, K=384
    sgemm_kernel<<<dim3(DIM / 128, DIM / 128, BATCH), 256>>>(
        scratch + OFF_C, (long)DIM * DIM, w_v, 0L,
        scratch + OFF_D, (long)DIM * DIM, DIM, DIM, DIM);

    // 7) out[b] = D[b] @ x[b] : M=384, N=4096, K=384
    sgemm_kernel<<<dim3(HW / 128, DIM / 128, BATCH), 256>>>(
        scratch + OFF_D, (long)DIM * DIM, x, (long)DIM * HW,
        out, (long)DIM * HW, DIM, HW, DIM);
}

// round 2
// speedup vs baseline: 3.2925x; 3.2925x over previous
#include <cuda_runtime.h>
#include <math.h>

// Problem constants
#define BATCH 16
#define DIM   384
#define QC    192
#define HW    4096
#define HEADS 8
#define DC    48
#define SPLIT 8
#define SLICE (HW / SPLIT)   // 512

// ---------------- scratch layout (floats) -----------------------------------
#define OFF_K    0L
#define OFF_Q    25165824L            // 16*384*4096
#define OFF_ATTN 50331648L            // + 16*384*4096
#define OFF_C    50626560L            // + 128*2304
#define OFF_D    52985856L            // + 16*384*384
#define OFF_PART 55345152L            // + 16*384*384
#define SCRATCH_TOTAL 57802752L       // + 128*8*2400

__device__ float g_scratch[SCRATCH_TOTAL];

// ---------------- helpers ---------------------------------------------------
__device__ __forceinline__ unsigned f2tf(float x) {
    unsigned r;
    asm("cvt.rna.tf32.f32 %0, %1;" : "=r"(r) : "f"(x));
    return r;
}

__device__ __forceinline__ void mma_tf32(float c[4], const unsigned a[4],
                                         const unsigned b[2]) {
    asm volatile(
        "mma.sync.aligned.m16n8k8.row.col.f32.tf32.tf32.f32 "
        "{%0,%1,%2,%3}, {%4,%5,%6,%7}, {%8,%9}, {%0,%1,%2,%3};\n"
        : "+f"(c[0]), "+f"(c[1]), "+f"(c[2]), "+f"(c[3])
        : "r"(a[0]), "r"(a[1]), "r"(a[2]), "r"(a[3]), "r"(b[0]), "r"(b[1]));
}

// ---------------- TF32 tensor-core GEMM: C = A @ B ---------------------------
// A [M,K] row-major, B [K,N] row-major, C [M,N]. Strides per batch (0 = shared).
// BM=BN=128, BK=32, 256 threads (8 warps, 2x4), warp tile 64x32, mma m16n8k8.
// Requires M%128==0, N%128==0, K%32==0.
__global__ __launch_bounds__(256) void gemm_tf32(
    const float* __restrict__ A, long sA,
    const float* __restrict__ B, long sB,
    float* __restrict__ C, long sC,
    int M, int N, int K)
{
    A += (long)blockIdx.z * sA;
    B += (long)blockIdx.z * sB;
    C += (long)blockIdx.z * sC;
    const int m0 = blockIdx.y * 128;
    const int n0 = blockIdx.x * 128;

    __shared__ unsigned As[128][36];   // [m][k], pad 4 -> conflict-free frags
    __shared__ unsigned Bs[32][136];   // [k][n], pad 8 -> conflict-free frags

    const int tid = threadIdx.x;
    const int warp = tid >> 5, lane = tid & 31;
    const int wm = warp >> 2, wn = warp & 3;
    const int g = lane >> 2, tig = lane & 3;

    float acc[4][4][4];
#pragma unroll
    for (int mt = 0; mt < 4; mt++)
#pragma unroll
        for (int nt = 0; nt < 4; nt++)
#pragma unroll
            for (int i = 0; i < 4; i++) acc[mt][nt][i] = 0.0f;

    for (int k0 = 0; k0 < K; k0 += 32) {
        // A tile: 128 rows x 32 cols
#pragma unroll
        for (int i = 0; i < 4; i++) {
            int f = tid + i * 256;
            int r = f >> 3, cv = (f & 7) * 4;
            float4 v = *(const float4*)(A + (long)(m0 + r) * K + k0 + cv);
            *(uint4*)&As[r][cv] =
                make_uint4(f2tf(v.x), f2tf(v.y), f2tf(v.z), f2tf(v.w));
        }
        // B tile: 32 rows x 128 cols
#pragma unroll
        for (int i = 0; i < 4; i++) {
            int f = tid + i * 256;
            int r = f >> 5, cv = (f & 31) * 4;
            float4 v = *(const float4*)(B + (long)(k0 + r) * N + n0 + cv);
            *(uint4*)&Bs[r][cv] =
                make_uint4(f2tf(v.x), f2tf(v.y), f2tf(v.z), f2tf(v.w));
        }
        __syncthreads();

#pragma unroll
        for (int kk = 0; kk < 32; kk += 8) {
            unsigned af[4][4], bf[4][2];
#pragma unroll
            for (int mt = 0; mt < 4; mt++) {
                int mr = wm * 64 + mt * 16;
                af[mt][0] = As[mr + g][kk + tig];
                af[mt][1] = As[mr + g + 8][kk + tig];
                af[mt][2] = As[mr + g][kk + tig + 4];
                af[mt][3] = As[mr + g + 8][kk + tig + 4];
            }
#pragma unroll
            for (int nt = 0; nt < 4; nt++) {
                int nc = wn * 32 + nt * 8 + g;
                bf[nt][0] = Bs[kk + tig][nc];
                bf[nt][1] = Bs[kk + tig + 4][nc];
            }
#pragma unroll
            for (int mt = 0; mt < 4; mt++)
#pragma unroll
                for (int nt = 0; nt < 4; nt++)
                    mma_tf32(acc[mt][nt], af[mt], bf[nt]);
        }
        __syncthreads();
    }

    // epilogue: float2 stores
#pragma unroll
    for (int mt = 0; mt < 4; mt++) {
        int m = m0 + wm * 64 + mt * 16 + g;
#pragma unroll
        for (int nt = 0; nt < 4; nt++) {
            int n = n0 + wn * 32 + nt * 8 + 2 * tig;
            *(float2*)(C + (long)m * N + n) =
                make_float2(acc[mt][nt][0], acc[mt][nt][1]);
            *(float2*)(C + (long)(m + 8) * N + n) =
                make_float2(acc[mt][nt][2], acc[mt][nt][3]);
        }
    }
}

// ---------------- attention partial: split-K logits + fused sumsq ------------
// grid (BATCH*HEADS, SPLIT), 256 threads. Each block: 48x48 partial S over a
// 512-wide spatial slice, plus per-row partial sum-of-squares for q and k.
__global__ __launch_bounds__(256) void attn_partial(float* __restrict__ scratch)
{
    const int bh = blockIdx.x, sp = blockIdx.y;
    const int b = bh >> 3, h = bh & 7;
    const float* qp = scratch + OFF_Q + ((long)b * DIM + h * DC) * HW + sp * SLICE;
    const float* kp = scratch + OFF_K + ((long)b * DIM + h * DC) * HW + sp * SLICE;
    float* part = scratch + OFF_PART + ((long)bh * SPLIT + sp) * 2400;

    __shared__ float qs[DC][33];
    __shared__ float ks[DC][33];

    const int tid = threadIdx.x;
    const int tx = tid & 15, ty = tid >> 4;
    const int lane = tid & 31, w = tid >> 5;

    float acc[3][3] = {{0, 0, 0}, {0, 0, 0}, {0, 0, 0}};
    float qn[6] = {0, 0, 0, 0, 0, 0}, kn[6] = {0, 0, 0, 0, 0, 0};

    for (int s0 = 0; s0 < SLICE; s0 += 32) {
#pragma unroll
        for (int i = 0; i < 6; i++) {
            int idx = tid + i * 256;
            int c = idx >> 5, kk = idx & 31;     // c = w + 8*i
            float qv = qp[(long)c * HW + s0 + kk];
            float kv = kp[(long)c * HW + s0 + kk];
            qs[c][kk] = qv;
            ks[c][kk] = kv;
            qn[i] += qv * qv;
            kn[i] += kv * kv;
        }
        __syncthreads();
#pragma unroll
        for (int kk = 0; kk < 32; kk++) {
            float qa[3], ka[3];
#pragma unroll
            for (int i = 0; i < 3; i++) qa[i] = qs[ty * 3 + i][kk];
#pragma unroll
            for (int j = 0; j < 3; j++) ka[j] = ks[tx * 3 + j][kk];
#pragma unroll
            for (int i = 0; i < 3; i++)
#pragma unroll
                for (int j = 0; j < 3; j++)
                    acc[i][j] = fmaf(qa[i], ka[j], acc[i][j]);
        }
        __syncthreads();
    }

    // write partial S
#pragma unroll
    for (int i = 0; i < 3; i++)
#pragma unroll
        for (int j = 0; j < 3; j++)
            part[(ty * 3 + i) * DC + tx * 3 + j] = acc[i][j];

    // warp-reduce row sumsq; row c = w + 8*i belongs entirely to warp w
#pragma unroll
    for (int i = 0; i < 6; i++) {
        float q = qn[i], k = kn[i];
#pragma unroll
        for (int o = 16; o; o >>= 1) {
            q += __shfl_xor_sync(0xFFFFFFFFu, q, o);
            k += __shfl_xor_sync(0xFFFFFFFFu, k, o);
        }
        if (lane == 0) {
            part[2304 + w + 8 * i] = q;
            part[2352 + w + 8 * i] = k;
        }
    }
}

// ---------------- attention reduce: sum partials, norms, softmax -------------
// grid BATCH*HEADS blocks, 256 threads.
__global__ __launch_bounds__(256) void attn_reduce(
    const float* __restrict__ temp, float* __restrict__ scratch)
{
    const int bh = blockIdx.x;
    const int h = bh & 7;
    const float* base = scratch + OFF_PART + (long)bh * SPLIT * 2400;
    float* aout = scratch + OFF_ATTN + (long)bh * DC * DC;

    __shared__ float S[DC * DC];
    __shared__ float rq[DC], rk[DC];

    const int tid = threadIdx.x;
#pragma unroll
    for (int j = 0; j < 9; j++) {
        int e = tid * 9 + j;                 // 256*9 = 2304 exactly
        float s = 0.0f;
#pragma unroll
        for (int sp = 0; sp < SPLIT; sp++) s += base[sp * 2400 + e];
        S[e] = s;
    }
    if (tid < 96) {
        float s = 0.0f;
#pragma unroll
        for (int sp = 0; sp < SPLIT; sp++) s += base[sp * 2400 + 2304 + tid];
        float inv = 1.0f / fmaxf(sqrtf(s), 1e-12f);
        if (tid < DC) rq[tid] = inv;
        else          rk[tid - DC] = inv;
    }
    __syncthreads();

    const float tsc = temp[h];
#pragma unroll
    for (int j = 0; j < 9; j++) {
        int e = tid * 9 + j;
        int c = e / DC, d = e % DC;
        S[e] *= rq[c] * rk[d] * tsc;
    }
    __syncthreads();

    if (tid < DC) {
        const int c = tid;
        float mx = -1e30f;
#pragma unroll
        for (int d = 0; d < DC; d++) mx = fmaxf(mx, S[c * DC + d]);
        float sum = 0.0f;
        float e[DC];
#pragma unroll
        for (int d = 0; d < DC; d++) {
            e[d] = expf(S[c * DC + d] - mx);
            sum += e[d];
        }
        float inv = 1.0f / sum;
#pragma unroll
        for (int d = 0; d < DC; d++) aout[c * DC + d] = e[d] * inv;
    }
}

// ---------------- fold: C[b] = W_proj @ blockdiag(attn[b]) -------------------
__global__ __launch_bounds__(256) void fold_kernel(
    const float* __restrict__ wp, float* __restrict__ scratch)
{
    const int b = blockIdx.y;
    const int idx = blockIdx.x * 256 + threadIdx.x;   // 0..147455
    const int o = idx / DIM, m = idx % DIM;
    const int h = m / DC, d = m % DC;
    const float* A = scratch + OFF_ATTN + ((long)b * HEADS + h) * DC * DC;
    const float* w = wp + (long)o * DIM + h * DC;
    float s = 0.0f;
#pragma unroll
    for (int c = 0; c < DC; c++) s = fmaf(w[c], A[c * DC + d], s);
    scratch[OFF_C + ((long)b * DIM + o) * DIM + m] = s;
}

// ---------------- launch ----------------------------------------------------
extern "C" void kernel_launch(void* const* d_in, const int* in_sizes, int n_in,
                              void* d_out, int out_size)
{
    const float* x      = (const float*)d_in[0];  // [16,384,64,64]
    const float* query  = (const float*)d_in[1];  // [16,192,64,64]
    const float* w_kv   = (const float*)d_in[2];  // [768,384]
    const float* w_q    = (const float*)d_in[3];  // [384,192]
    const float* w_proj = (const float*)d_in[4];  // [384,384]
    const float* temp   = (const float*)d_in[5];  // [8,1,1]
    float* out = (float*)d_out;                   // [16,384,64,64]

    float* scratch = nullptr;
    cudaGetSymbolAddress((void**)&scratch, g_scratch);

    const float* w_k = w_kv;                      // rows 0..383
    const float* w_v = w_kv + (long)DIM * DIM;    // rows 384..767

    // 1) k[b] = W_k @ x[b]   : M=384, N=4096, K=384
    gemm_tf32<<<dim3(HW / 128, DIM / 128, BATCH), 256>>>(
        w_k, 0L, x, (long)DIM * HW, scratch + OFF_K, (long)DIM * HW,
        DIM, HW, DIM);

    // 2) q[b] = W_q @ query[b] : M=384, N=4096, K=192
    gemm_tf32<<<dim3(HW / 128, DIM / 128, BATCH), 256>>>(
        w_q, 0L, query, (long)QC * HW, scratch + OFF_Q, (long)DIM * HW,
        DIM, HW, QC);

    // 3) split-K attention logits + fused row sumsq
    attn_partial<<<dim3(BATCH * HEADS, SPLIT), 256>>>(scratch);

    // 4) reduce partials, norms, softmax
    attn_reduce<<<BATCH * HEADS, 256>>>(temp, scratch);

    // 5) C[b] = W_proj @ blockdiag(attn[b])
    fold_kernel<<<dim3((DIM * DIM) / 256, BATCH), 256>>>(w_proj, scratch);

    // 6) D[b] = C[b] @ W_v  : M=384, N=384, K=384
    gemm_tf32<<<dim3(DIM / 128, DIM / 128, BATCH), 256>>>(
        scratch + OFF_C, (long)DIM * DIM, w_v, 0L,
        scratch + OFF_D, (long)DIM * DIM, DIM, DIM, DIM);

    // 7) out[b] = D[b] @ x[b] : M=384, N=4096, K=384
    gemm_tf32<<<dim3(HW / 128, DIM / 128, BATCH), 256>>>(
        scratch + OFF_D, (long)DIM * DIM, x, (long)DIM * HW,
        out, (long)DIM * HW, DIM, HW, DIM);
}